// round 5
// baseline (speedup 1.0000x reference)
#include <cuda_runtime.h>
#include <math.h>
#include <stdint.h>

#define BB 4
#define TT 2048
#define CC 1024
#define NH 16
#define HD 64
#define BT (BB*TT)      // 8192
#define C3 (3*CC)       // 3072

// Scratch (device globals; no allocation allowed)
__device__ float g_qkv[BT * C3];   // [BT, 3C]
__device__ float g_q[BT * CC];     // [B,H,T,64]  (tf32-rounded, pre-scaled 1/8)
__device__ float g_k[BT * CC];     // tf32-rounded
__device__ float g_v[BT * CC];     // tf32-rounded
__device__ float g_attn[BT * CC];  // [B,T,C]

// ---------------------------------------------------------------------------
// helpers
// ---------------------------------------------------------------------------
__device__ __forceinline__ unsigned f2tf(float x) {
    unsigned r;
    asm("cvt.rna.tf32.f32 %0, %1;" : "=r"(r) : "f"(x));
    return r;
}

// D = A(16x8) * B(8x8) + D  (tf32 in, fp32 accum), row.col
__device__ __forceinline__ void mma8(float* c, const unsigned* a,
                                     unsigned b0, unsigned b1) {
    asm("mma.sync.aligned.m16n8k8.row.col.f32.tf32.tf32.f32 "
        "{%0,%1,%2,%3}, {%4,%5,%6,%7}, {%8,%9}, {%0,%1,%2,%3};"
        : "+f"(c[0]), "+f"(c[1]), "+f"(c[2]), "+f"(c[3])
        : "r"(a[0]), "r"(a[1]), "r"(a[2]), "r"(a[3]), "r"(b0), "r"(b1));
}

__device__ __forceinline__ uint32_t sptr(const void* p) {
    return (uint32_t)__cvta_generic_to_shared(p);
}
__device__ __forceinline__ void cp16(uint32_t dst, const void* src) {
    asm volatile("cp.async.cg.shared.global [%0], [%1], 16;" :: "r"(dst), "l"(src));
}
__device__ __forceinline__ void cp_commit() {
    asm volatile("cp.async.commit_group;");
}
__device__ __forceinline__ void cp_wait0() {
    asm volatile("cp.async.wait_group 0;");
}
__device__ __forceinline__ void cp_wait1() {
    asm volatile("cp.async.wait_group 1;");
}

// ---------------------------------------------------------------------------
// tf32 tensor-core GEMM (unchanged from R4): 128x128x16 tiles, 8 warps.
// ---------------------------------------------------------------------------
__global__ __launch_bounds__(256) void gemm_tf32(
    const float* __restrict__ A, const float* __restrict__ Bm,
    float* __restrict__ Cm, int M, int N, int K)
{
    __shared__ unsigned As[16 * 136];
    __shared__ unsigned Bs[16 * 136];

    int tid = threadIdx.x;
    int lane = tid & 31;
    int warp = tid >> 5;
    int gid = lane >> 2, tig = lane & 3;
    int warp_m = warp >> 2, warp_n = warp & 3;
    int bm = blockIdx.y, bn = blockIdx.x;

    const float* Abase = A + (size_t)(bm * 128) * K;
    const float* Bbase = Bm + (size_t)bn * 128;

    float acc[4][4][4];
    #pragma unroll
    for (int mt = 0; mt < 4; mt++)
        #pragma unroll
        for (int nt = 0; nt < 4; nt++)
            #pragma unroll
            for (int e = 0; e < 4; e++) acc[mt][nt][e] = 0.f;

    int am = tid >> 2;
    int af4 = tid & 3;
    int bk = tid >> 5;
    int bn4 = (tid & 31) * 4;

    for (int k0 = 0; k0 < K; k0 += 16) {
        float4 a0v = *(const float4*)(Abase + (size_t)am * K + k0 + af4 * 4);
        float4 a1v = *(const float4*)(Abase + (size_t)(am + 64) * K + k0 + af4 * 4);
        float4 b0v = *(const float4*)(Bbase + (size_t)(k0 + bk) * N + bn4);
        float4 b1v = *(const float4*)(Bbase + (size_t)(k0 + bk + 8) * N + bn4);
        __syncthreads();
        {
            int swz = 8 * af4;
            int kb4 = af4 * 4;
            As[(kb4 + 0) * 136 + (am ^ swz)] = f2tf(a0v.x);
            As[(kb4 + 1) * 136 + (am ^ swz)] = f2tf(a0v.y);
            As[(kb4 + 2) * 136 + (am ^ swz)] = f2tf(a0v.z);
            As[(kb4 + 3) * 136 + (am ^ swz)] = f2tf(a0v.w);
            int am2 = am + 64;
            As[(kb4 + 0) * 136 + (am2 ^ swz)] = f2tf(a1v.x);
            As[(kb4 + 1) * 136 + (am2 ^ swz)] = f2tf(a1v.y);
            As[(kb4 + 2) * 136 + (am2 ^ swz)] = f2tf(a1v.z);
            As[(kb4 + 3) * 136 + (am2 ^ swz)] = f2tf(a1v.w);

            uint4 t0 = make_uint4(f2tf(b0v.x), f2tf(b0v.y), f2tf(b0v.z), f2tf(b0v.w));
            uint4 t1 = make_uint4(f2tf(b1v.x), f2tf(b1v.y), f2tf(b1v.z), f2tf(b1v.w));
            *(uint4*)&Bs[bk * 136 + bn4] = t0;
            *(uint4*)&Bs[(bk + 8) * 136 + bn4] = t1;
        }
        __syncthreads();

        #pragma unroll
        for (int ks = 0; ks < 16; ks += 8) {
            unsigned afr[4][4];
            unsigned bfr[4][2];
            int swz1 = 8 * ((ks >> 2) & 3);
            int swz2 = 8 * (((ks + 4) >> 2) & 3);
            #pragma unroll
            for (int mt = 0; mt < 4; mt++) {
                int m = warp_m * 64 + mt * 16 + gid;
                afr[mt][0] = As[(ks + tig) * 136 + (m ^ swz1)];
                afr[mt][1] = As[(ks + tig) * 136 + ((m + 8) ^ swz1)];
                afr[mt][2] = As[(ks + tig + 4) * 136 + (m ^ swz2)];
                afr[mt][3] = As[(ks + tig + 4) * 136 + ((m + 8) ^ swz2)];
            }
            #pragma unroll
            for (int nt = 0; nt < 4; nt++) {
                int n = warp_n * 32 + nt * 8 + gid;
                bfr[nt][0] = Bs[(ks + tig) * 136 + n];
                bfr[nt][1] = Bs[(ks + tig + 4) * 136 + n];
            }
            #pragma unroll
            for (int mt = 0; mt < 4; mt++)
                #pragma unroll
                for (int nt = 0; nt < 4; nt++)
                    mma8(acc[mt][nt], afr[mt], bfr[nt][0], bfr[nt][1]);
        }
    }

    #pragma unroll
    for (int mt = 0; mt < 4; mt++)
        #pragma unroll
        for (int nt = 0; nt < 4; nt++) {
            int row = bm * 128 + warp_m * 64 + mt * 16 + gid;
            int col = bn * 128 + warp_n * 32 + nt * 8 + tig * 2;
            *(float2*)&Cm[(size_t)row * N + col] =
                make_float2(acc[mt][nt][0], acc[mt][nt][1]);
            *(float2*)&Cm[(size_t)(row + 8) * N + col] =
                make_float2(acc[mt][nt][2], acc[mt][nt][3]);
        }
}

// ---------------------------------------------------------------------------
// Split qkv -> q,k,v in [B,H,T,64]; RoPE; tf32-round (rna) at write so the
// attention kernel can copy bytes verbatim (cp.async). Q pre-scaled by 1/8.
// ---------------------------------------------------------------------------
__global__ void rope_split_kernel()
{
    int idx = blockIdx.x * blockDim.x + threadIdx.x;
    const int total = BB * NH * TT * 32;
    if (idx >= total) return;

    int jj = idx & 31;
    int tmp = idx >> 5;
    int t = tmp & (TT - 1);
    tmp >>= 11;
    int h = tmp & (NH - 1);
    int b = tmp >> 4;

    const float LOG1E4 = 9.210340371976184f;
    float inv_freq = expf(-(float)jj * (LOG1E4 / 32.0f));
    float ang = (float)t * inv_freq;
    float cs = cosf(ang), sn = sinf(ang);

    size_t src_row = (size_t)(b * TT + t) * C3;
    int col = h * HD + jj;

    float q1 = g_qkv[src_row + col];
    float q2 = g_qkv[src_row + col + 32];
    float k1 = g_qkv[src_row + CC + col];
    float k2 = g_qkv[src_row + CC + col + 32];
    float v1 = g_qkv[src_row + 2 * CC + col];
    float v2 = g_qkv[src_row + 2 * CC + col + 32];

    size_t dst = ((size_t)(b * NH + h) * TT + t) * HD + jj;
    g_q[dst]      = __uint_as_float(f2tf((q1 * cs - q2 * sn) * 0.125f));
    g_q[dst + 32] = __uint_as_float(f2tf((q2 * cs + q1 * sn) * 0.125f));
    g_k[dst]      = __uint_as_float(f2tf(k1 * cs - k2 * sn));
    g_k[dst + 32] = __uint_as_float(f2tf(k2 * cs + k1 * sn));
    g_v[dst]      = __uint_as_float(f2tf(v1));
    g_v[dst + 32] = __uint_as_float(f2tf(v2));
}

// ---------------------------------------------------------------------------
// Flash attention (causal), tf32 mma, v2:
//  - Q fragments in registers (loaded once)
//  - P kept in registers; C-layout -> A-layout via intra-quad shuffles
//  - K/V in natural [kv][64] row-major smem (stride 72 words, conflict-free
//    for both S and PV B-fragments), double-buffered via cp.async.
// CTA = 128 queries, 8 warps; warp w owns rows [16w, 16w+16).
// Smem: sK[2][64*72] | sV[2][64*72]  = 72 KB.
// ---------------------------------------------------------------------------
#define KV_STR 72
#define KV_WORDS (64 * KV_STR)
#define ATTN_SMEM_WORDS (4 * KV_WORDS)

__global__ __launch_bounds__(256) void attn_mma_kernel()
{
    extern __shared__ float sm[];
    float* sK[2] = { sm, sm + KV_WORDS };
    float* sV[2] = { sm + 2 * KV_WORDS, sm + 3 * KV_WORDS };

    int tid = threadIdx.x;
    int lane = tid & 31;
    int warp = tid >> 5;
    int gid = lane >> 2, tig = lane & 3;
    int qb = blockIdx.x;       // 0..15  (128 queries each)
    int bh = blockIdx.y;       // b*NH + h

    const float* Qg = g_q + ((size_t)bh * TT + qb * 128) * HD;
    const float* Kg = g_k + (size_t)bh * TT * HD;
    const float* Vg = g_v + (size_t)bh * TT * HD;

    int m_local = warp * 16 + gid;
    int row1 = qb * 128 + m_local;
    int row2 = row1 + 8;

    // Q fragments, loaded once (values already tf32-rounded & scaled)
    unsigned qa[8][4];
    #pragma unroll
    for (int c = 0; c < 8; c++) {
        qa[c][0] = __float_as_uint(Qg[(size_t)m_local * 64 + c * 8 + tig]);
        qa[c][1] = __float_as_uint(Qg[(size_t)(m_local + 8) * 64 + c * 8 + tig]);
        qa[c][2] = __float_as_uint(Qg[(size_t)m_local * 64 + c * 8 + tig + 4]);
        qa[c][3] = __float_as_uint(Qg[(size_t)(m_local + 8) * 64 + c * 8 + tig + 4]);
    }

    float oacc[8][4];
    #pragma unroll
    for (int nt = 0; nt < 8; nt++)
        #pragma unroll
        for (int e = 0; e < 4; e++) oacc[nt][e] = 0.f;
    float rm0 = -1e30f, rm1 = -1e30f, rl0 = 0.f, rl1 = 0.f;

    int kb_max = 2 * qb + 1;

    // issue tile 0 into buffer 0
    {
        #pragma unroll
        for (int it = 0; it < 4; it++) {
            int cid = tid + 256 * it;
            int r = cid >> 4;
            int c4 = (cid & 15) * 4;       // word offset in row
            cp16(sptr(sK[0] + r * KV_STR + c4), Kg + (size_t)r * 64 + c4);
            cp16(sptr(sV[0] + r * KV_STR + c4), Vg + (size_t)r * 64 + c4);
        }
        cp_commit();
    }

    for (int kb = 0; kb <= kb_max; kb++) {
        int cur = kb & 1;
        bool has_next = (kb < kb_max);
        if (has_next) {
            int nb = cur ^ 1;
            const float* Kn = Kg + (size_t)(kb + 1) * 64 * 64;
            const float* Vn = Vg + (size_t)(kb + 1) * 64 * 64;
            #pragma unroll
            for (int it = 0; it < 4; it++) {
                int cid = tid + 256 * it;
                int r = cid >> 4;
                int c4 = (cid & 15) * 4;
                cp16(sptr(sK[nb] + r * KV_STR + c4), Kn + (size_t)r * 64 + c4);
                cp16(sptr(sV[nb] + r * KV_STR + c4), Vn + (size_t)r * 64 + c4);
            }
            cp_commit();
            cp_wait1();          // tile kb complete (kb+1 may be in flight)
        } else {
            cp_wait0();
        }
        __syncthreads();

        const float* K_ = sK[cur];
        const float* V_ = sV[cur];

        // S = Q K^T for my 16-row strip (16 x 64)
        float sacc[8][4];
        #pragma unroll
        for (int nt = 0; nt < 8; nt++)
            #pragma unroll
            for (int e = 0; e < 4; e++) sacc[nt][e] = 0.f;

        #pragma unroll
        for (int c = 0; c < 8; c++) {
            int ks = c * 8;
            #pragma unroll
            for (int nt = 0; nt < 8; nt++) {
                int n = nt * 8 + gid;
                unsigned b0 = __float_as_uint(K_[n * KV_STR + ks + tig]);
                unsigned b1 = __float_as_uint(K_[n * KV_STR + ks + tig + 4]);
                mma8(sacc[nt], qa[c], b0, b1);
            }
        }

        // causal mask
        if (kb >= 2 * qb) {
            #pragma unroll
            for (int nt = 0; nt < 8; nt++) {
                int colb = kb * 64 + nt * 8 + tig * 2;
                if (colb + 0 > row1) sacc[nt][0] = -1e30f;
                if (colb + 1 > row1) sacc[nt][1] = -1e30f;
                if (colb + 0 > row2) sacc[nt][2] = -1e30f;
                if (colb + 1 > row2) sacc[nt][3] = -1e30f;
            }
        }

        // online softmax (quad reductions)
        float mx0 = -1e30f, mx1 = -1e30f;
        #pragma unroll
        for (int nt = 0; nt < 8; nt++) {
            mx0 = fmaxf(mx0, fmaxf(sacc[nt][0], sacc[nt][1]));
            mx1 = fmaxf(mx1, fmaxf(sacc[nt][2], sacc[nt][3]));
        }
        mx0 = fmaxf(mx0, __shfl_xor_sync(0xffffffffu, mx0, 1));
        mx0 = fmaxf(mx0, __shfl_xor_sync(0xffffffffu, mx0, 2));
        mx1 = fmaxf(mx1, __shfl_xor_sync(0xffffffffu, mx1, 1));
        mx1 = fmaxf(mx1, __shfl_xor_sync(0xffffffffu, mx1, 2));

        float mn0 = fmaxf(rm0, mx0);
        float mn1 = fmaxf(rm1, mx1);
        float corr0 = __expf(rm0 - mn0);
        float corr1 = __expf(rm1 - mn1);
        rm0 = mn0; rm1 = mn1;

        float sum0 = 0.f, sum1 = 0.f;
        #pragma unroll
        for (int nt = 0; nt < 8; nt++) {
            sacc[nt][0] = __expf(sacc[nt][0] - mn0);
            sacc[nt][1] = __expf(sacc[nt][1] - mn0);
            sacc[nt][2] = __expf(sacc[nt][2] - mn1);
            sacc[nt][3] = __expf(sacc[nt][3] - mn1);
            sum0 += sacc[nt][0] + sacc[nt][1];
            sum1 += sacc[nt][2] + sacc[nt][3];
        }
        sum0 += __shfl_xor_sync(0xffffffffu, sum0, 1);
        sum0 += __shfl_xor_sync(0xffffffffu, sum0, 2);
        sum1 += __shfl_xor_sync(0xffffffffu, sum1, 1);
        sum1 += __shfl_xor_sync(0xffffffffu, sum1, 2);
        rl0 = rl0 * corr0 + sum0;
        rl1 = rl1 * corr1 + sum1;

        #pragma unroll
        for (int nt = 0; nt < 8; nt++) {
            oacc[nt][0] *= corr0; oacc[nt][1] *= corr0;
            oacc[nt][2] *= corr1; oacc[nt][3] *= corr1;
        }

        // O += P @ V. A-frag for k-chunk c built from sacc[c] via quad shuffles:
        // C-layout holds cols 2tig,2tig+1; A-layout needs cols tig, tig+4.
        int base = lane & 28;                 // quad base lane
        int src0 = base + (tig >> 1);
        int src2 = src0 + 2;
        int odd = tig & 1;
        #pragma unroll
        for (int c = 0; c < 8; c++) {
            float e0 = __shfl_sync(0xffffffffu, sacc[c][0], src0);
            float e1 = __shfl_sync(0xffffffffu, sacc[c][1], src0);
            float g0 = __shfl_sync(0xffffffffu, sacc[c][0], src2);
            float g1 = __shfl_sync(0xffffffffu, sacc[c][1], src2);
            float f0 = __shfl_sync(0xffffffffu, sacc[c][2], src0);
            float f1 = __shfl_sync(0xffffffffu, sacc[c][3], src0);
            float h0 = __shfl_sync(0xffffffffu, sacc[c][2], src2);
            float h1 = __shfl_sync(0xffffffffu, sacc[c][3], src2);
            unsigned pa[4];
            pa[0] = f2tf(odd ? e1 : e0);      // P[r1][8c+tig]
            pa[1] = f2tf(odd ? f1 : f0);      // P[r2][8c+tig]
            pa[2] = f2tf(odd ? g1 : g0);      // P[r1][8c+tig+4]
            pa[3] = f2tf(odd ? h1 : h0);      // P[r2][8c+tig+4]
            int ks = c * 8;
            #pragma unroll
            for (int dt = 0; dt < 8; dt++) {
                int n = dt * 8 + gid;
                unsigned b0 = __float_as_uint(V_[(ks + tig) * KV_STR + n]);
                unsigned b1 = __float_as_uint(V_[(ks + tig + 4) * KV_STR + n]);
                mma8(oacc[dt], pa, b0, b1);
            }
        }
        __syncthreads();   // everyone done with buffer `cur` before it is refilled
    }

    // epilogue: normalize, write to [B,T,C]
    int b = bh >> 4;
    int h = bh & (NH - 1);
    float il0 = 1.f / rl0;
    float il1 = 1.f / rl1;
    #pragma unroll
    for (int nt = 0; nt < 8; nt++) {
        int d = nt * 8 + tig * 2;
        *(float2*)&g_attn[((size_t)(b * TT + row1)) * CC + h * 64 + d] =
            make_float2(oacc[nt][0] * il0, oacc[nt][1] * il0);
        *(float2*)&g_attn[((size_t)(b * TT + row2)) * CC + h * 64 + d] =
            make_float2(oacc[nt][2] * il1, oacc[nt][3] * il1);
    }
}

// ---------------------------------------------------------------------------
extern "C" void kernel_launch(void* const* d_in, const int* in_sizes, int n_in,
                              void* d_out, int out_size)
{
    const float* x     = (const float*)d_in[0];
    const float* w_qkv = (const float*)d_in[1];
    const float* w_out = (const float*)d_in[2];
    float* out = (float*)d_out;

    float *qkv_p, *attn_p;
    cudaGetSymbolAddress((void**)&qkv_p,  g_qkv);
    cudaGetSymbolAddress((void**)&attn_p, g_attn);

    // 1) QKV projection
    {
        dim3 grid(C3 / 128, BT / 128);
        gemm_tf32<<<grid, 256>>>(x, w_qkv, qkv_p, BT, C3, CC);
    }

    // 2) split + RoPE (+ tf32 rounding)
    {
        int total = BB * NH * TT * 32;
        rope_split_kernel<<<(total + 255) / 256, 256>>>();
    }

    // 3) flash attention (tensor cores, cp.async double-buffered)
    {
        int smem_bytes = ATTN_SMEM_WORDS * sizeof(float);
        cudaFuncSetAttribute(attn_mma_kernel,
                             cudaFuncAttributeMaxDynamicSharedMemorySize,
                             smem_bytes);
        dim3 grid(TT / 128, BB * NH);
        attn_mma_kernel<<<grid, 256, smem_bytes>>>();
    }

    // 4) output projection
    {
        dim3 grid(CC / 128, BT / 128);
        gemm_tf32<<<grid, 256>>>(attn_p, w_out, out, BT, CC, CC);
    }
}